// round 6
// baseline (speedup 1.0000x reference)
#include <cuda_runtime.h>

#define NB 32
#define NS 4096
#define ND 1024
#define NEGV -1e37f

#define SCHUNK 256
#define NCH (NS / SCHUNK)   // 16

// unnormalized partial PV sums [B, NCH, D], plus per-chunk max / sum
__device__ float g_part[NB * NCH * ND];
__device__ float g_m[NB * NCH];
__device__ float g_s[NB * NCH];

// ---------------------------------------------------------------------------
// Fused kernel: one block = (b, 256-row s-chunk).
//  Phase A: 8 warps, each 32 rows (2 at a time for MLP): logit = q.k, masked
//           rows skip the K read and get -1e37.
//  Local softmax: chunk max m_c, weights exp(l - m_c), local sum s_c.
//  Phase B: acc_d = sum_i w_i * V[i,d], skipping rows with w == 0.
//  Writes unnormalized partials; merge kernel rescales across chunks.
// ---------------------------------------------------------------------------
__global__ __launch_bounds__(256) void fused_kernel(
    const float* __restrict__ keys,
    const float* __restrict__ queries,
    const float* __restrict__ values,
    const int*   __restrict__ mask)
{
    int chunk = blockIdx.x & (NCH - 1);
    int b     = blockIdx.x / NCH;
    int s0    = chunk * SCHUNK;

    __shared__ float4 qs[ND / 4];       // 256 float4 = full q row
    __shared__ float  ls[SCHUNK];       // logits, then weights
    __shared__ float  red[8];

    int t    = threadIdx.x;
    int warp = t >> 5;
    int lane = t & 31;

    qs[t] = ((const float4*)(queries + (size_t)b * ND))[t];
    __syncthreads();

    // ---------------- Phase A: logits (2 rows per warp iteration) ----------
    const int* mrow = mask + b * NS + s0;
#pragma unroll 1
    for (int r = 0; r < 32; r += 2) {
        int sl0 = warp * 32 + r;
        int sl1 = sl0 + 1;
        bool v0 = mrow[sl0] != 0;
        bool v1 = mrow[sl1] != 0;

        const float4* k0 = (const float4*)(keys + ((size_t)b * NS + s0 + sl0) * ND);
        const float4* k1 = (const float4*)(keys + ((size_t)b * NS + s0 + sl1) * ND);

        float a0 = 0.f, a1 = 0.f;
#pragma unroll
        for (int i = 0; i < 8; i++) {
            int idx = i * 32 + lane;
            float4 qv = qs[idx];
            if (v0) {
                float4 kv = __ldcs(&k0[idx]);
                a0 += kv.x * qv.x + kv.y * qv.y + kv.z * qv.z + kv.w * qv.w;
            }
            if (v1) {
                float4 kv = __ldcs(&k1[idx]);
                a1 += kv.x * qv.x + kv.y * qv.y + kv.z * qv.z + kv.w * qv.w;
            }
        }
#pragma unroll
        for (int o = 16; o; o >>= 1) {
            a0 += __shfl_xor_sync(0xFFFFFFFFu, a0, o);
            a1 += __shfl_xor_sync(0xFFFFFFFFu, a1, o);
        }
        if (lane == 0) {
            ls[sl0] = v0 ? a0 : NEGV;
            ls[sl1] = v1 ? a1 : NEGV;
        }
    }
    __syncthreads();

    // ---------------- local max over 256 logits ----------------------------
    float lv = ls[t];
    float m = lv;
#pragma unroll
    for (int o = 16; o; o >>= 1) m = fmaxf(m, __shfl_xor_sync(0xFFFFFFFFu, m, o));
    if (lane == 0) red[warp] = m;
    __syncthreads();
    if (t < 32) {
        float x = (lane < 8) ? red[lane] : NEGV;
#pragma unroll
        for (int o = 4; o; o >>= 1) x = fmaxf(x, __shfl_xor_sync(0xFFFFFFFFu, x, o));
        if (lane == 0) red[0] = x;
    }
    __syncthreads();
    m = red[0];
    bool chunk_valid = (m != NEGV);
    __syncthreads();

    // ---------------- weights + local sum -----------------------------------
    float w = chunk_valid ? __expf(lv - m) : 0.f;   // masked rows underflow to 0
    ls[t] = w;
    float s = w;
#pragma unroll
    for (int o = 16; o; o >>= 1) s += __shfl_xor_sync(0xFFFFFFFFu, s, o);
    if (lane == 0) red[warp] = s;
    __syncthreads();
    if (t == 0) {
        float tot = 0.f;
#pragma unroll
        for (int i = 0; i < 8; i++) tot += red[i];
        g_m[b * NCH + chunk] = m;
        g_s[b * NCH + chunk] = tot;
    }
    __syncthreads();

    // ---------------- Phase B: weighted V partial ---------------------------
    const float4* v4 = (const float4*)(values + ((size_t)b * NS + s0) * ND);
    float4 acc = make_float4(0.f, 0.f, 0.f, 0.f);

#pragma unroll 4
    for (int i = 0; i < SCHUNK; i += 4) {
        float w0 = ls[i], w1 = ls[i + 1], w2 = ls[i + 2], w3 = ls[i + 3];
        float4 a = make_float4(0.f, 0.f, 0.f, 0.f);
        float4 c = make_float4(0.f, 0.f, 0.f, 0.f);
        float4 d = make_float4(0.f, 0.f, 0.f, 0.f);
        float4 e = make_float4(0.f, 0.f, 0.f, 0.f);
        if (w0 != 0.f) a = __ldcs(&v4[(size_t)(i + 0) * (ND / 4) + t]);
        if (w1 != 0.f) c = __ldcs(&v4[(size_t)(i + 1) * (ND / 4) + t]);
        if (w2 != 0.f) d = __ldcs(&v4[(size_t)(i + 2) * (ND / 4) + t]);
        if (w3 != 0.f) e = __ldcs(&v4[(size_t)(i + 3) * (ND / 4) + t]);
        acc.x += w0 * a.x; acc.y += w0 * a.y; acc.z += w0 * a.z; acc.w += w0 * a.w;
        acc.x += w1 * c.x; acc.y += w1 * c.y; acc.z += w1 * c.z; acc.w += w1 * c.w;
        acc.x += w2 * d.x; acc.y += w2 * d.y; acc.z += w2 * d.z; acc.w += w2 * d.w;
        acc.x += w3 * e.x; acc.y += w3 * e.y; acc.z += w3 * e.z; acc.w += w3 * e.w;
    }

    ((float4*)g_part)[(size_t)(b * NCH + chunk) * (ND / 4) + t] = acc;
}

// ---------------------------------------------------------------------------
// Merge: out[b,d] = sum_c exp(m_c - M) * part[b,c,d] / sum_c exp(m_c - M)*s_c
// One block per b, 256 threads (one float4 of D each).
// ---------------------------------------------------------------------------
__global__ __launch_bounds__(256) void merge_kernel(float* __restrict__ out)
{
    int b = blockIdx.x;
    int t = threadIdx.x;

    __shared__ float coef[NCH];
    __shared__ float sden;

    if (t < 32) {
        float mv = (t < NCH) ? g_m[b * NCH + t] : -3.4e38f;
        float M = mv;
#pragma unroll
        for (int o = 16; o; o >>= 1) M = fmaxf(M, __shfl_xor_sync(0xFFFFFFFFu, M, o));
        float cv = (t < NCH) ? __expf(mv - M) : 0.f;
        float dv = (t < NCH) ? cv * g_s[b * NCH + t] : 0.f;
#pragma unroll
        for (int o = 16; o; o >>= 1) dv += __shfl_xor_sync(0xFFFFFFFFu, dv, o);
        if (t < NCH) coef[t] = cv;
        if (t == 0)  sden = dv;
    }
    __syncthreads();

    float inv = 1.0f / sden;
    const float4* p4 = (const float4*)g_part + (size_t)b * NCH * (ND / 4);
    float4 acc = make_float4(0.f, 0.f, 0.f, 0.f);
#pragma unroll
    for (int c = 0; c < NCH; c++) {
        float w = coef[c];
        float4 v = p4[(size_t)c * (ND / 4) + t];
        acc.x += w * v.x; acc.y += w * v.y; acc.z += w * v.z; acc.w += w * v.w;
    }
    acc.x *= inv; acc.y *= inv; acc.z *= inv; acc.w *= inv;
    ((float4*)out)[(size_t)b * (ND / 4) + t] = acc;
}

// ---------------------------------------------------------------------------
extern "C" void kernel_launch(void* const* d_in, const int* in_sizes, int n_in,
                              void* d_out, int out_size)
{
    const float* keys    = (const float*)d_in[0];
    const float* queries = (const float*)d_in[1];
    const float* values  = (const float*)d_in[2];
    const int*   mask    = (const int*)d_in[3];
    float* out = (float*)d_out;

    fused_kernel<<<NB * NCH, 256>>>(keys, queries, values, mask);
    merge_kernel<<<NB, 256>>>(out);
}